// round 17
// baseline (speedup 1.0000x reference)
#include <cuda_runtime.h>

// Gaussian-splat over-compositing, N pixels x K gaussians, sm_103a.
// R17: two-kernel split.
//  Kernel 1 (cheap, all pixels): drop the per-step renormalization factor
//   g = pa/(pa+eps) entirely:
//     e = ex2(quad); w = fma(-d, e, e); u_c += col_c*w; d += w
//   d (hence alpha) is EXACT (g never affected d). Color error bound
//   (telescoping): |du| <= 255*K*eps = 3.3e-4 abs -> |dpc| <= 3.3e-4/(pa+eps).
//  Kernel 2 (fixup): pixels with pa < 0.01 recomputed with the exact R13
//   recurrence (u = u*g + col*w; g = 1-eps*rcp(d)). Blocks with no flagged
//   pixel exit after one coalesced read (__syncthreads_or).

#define MAXK 128
#define EPSC 1e-8f
#define PA_W_THRESH (0.01f * 255.0f)   // flag if alpha channel < this

__device__ __forceinline__ float ex2f_(float x) {
    float y; asm("ex2.approx.f32 %0, %1;" : "=f"(y) : "f"(x)); return y;
}
__device__ __forceinline__ float rcpf_(float x) {
    float y; asm("rcp.approx.f32 %0, %1;" : "=f"(y) : "f"(x)); return y;
}

// smem: spAB[k] = {A,B2,C,Dx}; spEF[k] = {Ey,F,c0,c1}; sc2v[k/4] = 4x c2
__device__ __forceinline__ void prep_params(float4* spAB, float4* spEF,
                                            float* sc2,
                                            const float* mu, const float* alpha,
                                            const float* color, const float* scales,
                                            const float* thetas, int K) {
    const float L2E = 1.44269504088896340736f;
    for (int k = threadIdx.x; k < K; k += blockDim.x) {
        float th = thetas[k];
        float c = cosf(th), s = sinf(th);
        float sx = fmaxf(scales[2 * k + 0], 0.1f);
        float sy = fmaxf(scales[2 * k + 1], 0.1f);
        float ix = 1.0f / (sx * sx);
        float iy = 1.0f / (sy * sy);
        float S00 = c * c * ix + s * s * iy;
        float S01 = c * s * (ix - iy);
        float S11 = s * s * ix + c * c * iy;
        float h = -0.5f * L2E;
        float A  = h * S00;
        float B2 = (2.0f * h) * S01;
        float C  = h * S11;
        float a  = fminf(fmaxf(alpha[k], 0.0f), 1.0f);
        float la = log2f(fmaxf(a, 1e-38f));
        float c0 = fminf(fmaxf(color[3 * k + 0], 0.0f), 255.0f);
        float c1 = fminf(fmaxf(color[3 * k + 1], 0.0f), 255.0f);
        float c2 = fminf(fmaxf(color[3 * k + 2], 0.0f), 255.0f);
        float mx = mu[2 * k + 0] - 256.0f;   // centered coords
        float my = mu[2 * k + 1] - 256.0f;
        float Dx = -(2.0f * A * mx + B2 * my);
        float Ey = -(B2 * mx + 2.0f * C * my);
        float F  = (A * mx * mx + B2 * mx * my + C * my * my) + la;
        spAB[k] = make_float4(A, B2, C, Dx);
        spEF[k] = make_float4(Ey, F, c0, c1);
        sc2[k]  = c2;
    }
}

// ---------------- kernel 1: cheap pass (no per-step renormalization) -------
template<int KT>
__global__ __launch_bounds__(128)
void gs_main(const float* __restrict__ pos,
             const float* __restrict__ mu,
             const float* __restrict__ alpha,
             const float* __restrict__ color,
             const float* __restrict__ scales,
             const float* __restrict__ thetas,
             float4* __restrict__ out,
             int n, int K)
{
    __shared__ __align__(16) float4 spAB[MAXK];
    __shared__ __align__(16) float4 spEF[MAXK];
    __shared__ __align__(16) float4 sc2v[MAXK / 4];
    prep_params(spAB, spEF, (float*)sc2v, mu, alpha, color, scales, thetas, K);
    __syncthreads();

    int i = blockIdx.x * blockDim.x + threadIdx.x;
    bool valid = (i < n);
    const float2* pos2 = (const float2*)pos;
    float2 P = valid ? pos2[i] : make_float2(0.0f, 0.0f);

    float X = P.x - 256.0f;
    float Y = P.y - 256.0f;
    float X2 = X * X;
    float XY = X * Y;
    float Y2 = Y * Y;

    float u0 = 0.0f, u1 = 0.0f, u2 = 0.0f;
    float d  = EPSC;                          // pa + eps (exact)

    if (KT == 128) {
#pragma unroll 4
        for (int kb = 0; kb < 128; kb += 4) {
            float4 c2v = sc2v[kb >> 2];
#pragma unroll
            for (int j = 0; j < 4; j++) {
                int k = kb + j;
                float c2 = (j == 0) ? c2v.x : (j == 1) ? c2v.y
                         : (j == 2) ? c2v.z : c2v.w;
                float4 p0 = spAB[k];
                float4 p1 = spEF[k];

                float t = fmaf(p1.x, Y, p1.y);
                t = fmaf(p0.w, X, t);
                t = fmaf(p0.z, Y2, t);
                t = fmaf(p0.y, XY, t);
                float q = fmaf(p0.x, X2, t);

                float e = ex2f_(q);
                float w = fmaf(-d, e, e);      // e*(1-d)
                u0 = fmaf(p1.z, w, u0);
                u1 = fmaf(p1.w, w, u1);
                u2 = fmaf(c2,   w, u2);
                d += w;
            }
        }
    } else {
        const float* sc2 = (const float*)sc2v;
        for (int k = 0; k < K; k++) {
            float4 p0 = spAB[k];
            float4 p1 = spEF[k];
            float c2  = sc2[k];
            float t = fmaf(p1.x, Y, p1.y);
            t = fmaf(p0.w, X, t);
            t = fmaf(p0.z, Y2, t);
            t = fmaf(p0.y, XY, t);
            float q = fmaf(p0.x, X2, t);
            float e = ex2f_(q);
            float w = fmaf(-d, e, e);
            u0 = fmaf(p1.z, w, u0);
            u1 = fmaf(p1.w, w, u1);
            u2 = fmaf(c2,   w, u2);
            d += w;
        }
    }

    if (valid) {
        float r  = rcpf_(d);
        float pa = d - EPSC;
        out[i] = make_float4(fminf(fmaxf(u0 * r, 0.0f), 255.0f),
                             fminf(fmaxf(u1 * r, 0.0f), 255.0f),
                             fminf(fmaxf(u2 * r, 0.0f), 255.0f),
                             fminf(fmaxf(pa, 0.0f), 1.0f) * 255.0f);
    }
}

// ---------------- kernel 2: exact fixup for low-alpha pixels ---------------
__global__ __launch_bounds__(128)
void gs_fixup(const float* __restrict__ pos,
              const float* __restrict__ mu,
              const float* __restrict__ alpha,
              const float* __restrict__ color,
              const float* __restrict__ scales,
              const float* __restrict__ thetas,
              float4* __restrict__ out,
              int n, int K)
{
    int i = blockIdx.x * blockDim.x + threadIdx.x;
    bool valid = (i < n);
    float paw = valid ? out[i].w : 255.0f;     // alpha channel = clamp(pa)*255
    bool flag = valid && (paw < PA_W_THRESH);

    if (!__syncthreads_or((int)flag)) return;  // whole block clean -> exit

    __shared__ __align__(16) float4 spAB[MAXK];
    __shared__ __align__(16) float4 spEF[MAXK];
    __shared__ __align__(16) float4 sc2v[MAXK / 4];
    prep_params(spAB, spEF, (float*)sc2v, mu, alpha, color, scales, thetas, K);
    __syncthreads();

    if (!flag) return;

    const float2* pos2 = (const float2*)pos;
    float2 P = pos2[i];
    float X = P.x - 256.0f;
    float Y = P.y - 256.0f;
    float X2 = X * X, XY = X * Y, Y2 = Y * Y;

    const float* sc2 = (const float*)sc2v;
    float u0 = 0.0f, u1 = 0.0f, u2 = 0.0f;
    float d  = EPSC;
    float gC = 0.0f;
    float rC = 0.0f;

#pragma unroll 4
    for (int k = 0; k < K; k++) {              // exact R13 recurrence
        float4 p0 = spAB[k];
        float4 p1 = spEF[k];
        float c2  = sc2[k];

        float t = fmaf(p1.x, Y, p1.y);
        t = fmaf(p0.w, X, t);
        t = fmaf(p0.z, Y2, t);
        t = fmaf(p0.y, XY, t);
        float q = fmaf(p0.x, X2, t);

        float e = ex2f_(q);
        float w = fmaf(-d, e, e);
        u0 = fmaf(u0, gC, p1.z * w);
        u1 = fmaf(u1, gC, p1.w * w);
        u2 = fmaf(u2, gC, c2 * w);
        d += w;
        rC = rcpf_(d);
        gC = fmaf(rC, -EPSC, 1.0f);
    }

    float pa = d - EPSC;
    out[i] = make_float4(fminf(fmaxf(u0 * rC, 0.0f), 255.0f),
                         fminf(fmaxf(u1 * rC, 0.0f), 255.0f),
                         fminf(fmaxf(u2 * rC, 0.0f), 255.0f),
                         fminf(fmaxf(pa, 0.0f), 1.0f) * 255.0f);
}

extern "C" void kernel_launch(void* const* d_in, const int* in_sizes, int n_in,
                              void* d_out, int out_size)
{
    const float* pos    = (const float*)d_in[0];
    const float* mu     = (const float*)d_in[1];
    const float* alpha  = (const float*)d_in[2];
    const float* color  = (const float*)d_in[3];
    const float* scales = (const float*)d_in[4];
    const float* thetas = (const float*)d_in[5];

    int n = in_sizes[0] / 2;     // pixels
    int K = in_sizes[2];         // gaussians
    if (K > MAXK) K = MAXK;

    const int threads = 128;
    int grid = (n + threads - 1) / threads;

    if (K == 128) {
        gs_main<128><<<grid, threads>>>(pos, mu, alpha, color, scales,
                                        thetas, (float4*)d_out, n, K);
    } else {
        gs_main<0><<<grid, threads>>>(pos, mu, alpha, color, scales,
                                      thetas, (float4*)d_out, n, K);
    }
    gs_fixup<<<grid, threads>>>(pos, mu, alpha, color, scales,
                                thetas, (float4*)d_out, n, K);
}